// round 17
// baseline (speedup 1.0000x reference)
#include <cuda_runtime.h>

#define BB     64
#define CC     256
#define HH     56
#define WW     56
#define HW     3136
#define NROWS  (BB*CC)        // 16384
#define TOPK   38
#define NSEL   (BB*TOPK)      // 2432
#define MAIN4  768            // 784 float4/row = 6*128 + 16
#define QW     196            // float4 per quarter-row

__device__ float g_sums[NROWS];
__device__ int   g_amax[NROWS];
__device__ int4  g_task[NSEL];   // {row, aidx, lam_bits, 0}

__device__ __forceinline__ void quad_max(float4 v, int p, float& mval, int& midx) {
    const float m4 = fmaxf(fmaxf(v.x, v.y), fmaxf(v.z, v.w));
    if (m4 > mval) {
        mval = m4;
        midx = p + ((v.x == m4) ? 0 : (v.y == m4) ? 1 : (v.z == m4) ? 2 : 3);
    }
}

// ---------------------------------------------------------------------------
// K1: warp-per-row, unroll-by-4, pure streaming (ldcs/stcs), no fences.
// Measured at the mixed-R/W HBM ceiling (74-75% DRAM across 7 configs).
// ---------------------------------------------------------------------------
__global__ __launch_bounds__(256) void k1_reduce_copy(const float* __restrict__ x,
                                                      float* __restrict__ out) {
    const int warp = threadIdx.x >> 5;
    const int lane = threadIdx.x & 31;
    const int row  = blockIdx.x * 8 + warp;

    const float4* __restrict__ xr  = (const float4*)(x   + (size_t)row * HW);
    float4*       __restrict__ orr = (float4*)      (out + (size_t)row * HW);

    float s0 = 0.f, s1 = 0.f, s2 = 0.f, s3 = 0.f;
    float mval = -3.402823466e38f;
    int   midx = 0;

    #pragma unroll
    for (int base = 0; base < MAIN4; base += 128) {
        const int i0 = base + lane;
        float4 a = __ldcs(&xr[i0]);
        float4 b = __ldcs(&xr[i0 + 32]);
        float4 c = __ldcs(&xr[i0 + 64]);
        float4 d = __ldcs(&xr[i0 + 96]);
        __stcs(&orr[i0],      a);
        __stcs(&orr[i0 + 32], b);
        __stcs(&orr[i0 + 64], c);
        __stcs(&orr[i0 + 96], d);
        s0 += a.x + a.y + a.z + a.w;
        s1 += b.x + b.y + b.z + b.w;
        s2 += c.x + c.y + c.z + c.w;
        s3 += d.x + d.y + d.z + d.w;
        quad_max(a, (i0)      << 2, mval, midx);
        quad_max(b, (i0 + 32) << 2, mval, midx);
        quad_max(c, (i0 + 64) << 2, mval, midx);
        quad_max(d, (i0 + 96) << 2, mval, midx);
    }
    if (lane < 16) {
        const int i0 = MAIN4 + lane;
        float4 a = __ldcs(&xr[i0]);
        __stcs(&orr[i0], a);
        s0 += a.x + a.y + a.z + a.w;
        quad_max(a, i0 << 2, mval, midx);
    }

    float sum = (s0 + s1) + (s2 + s3);
    #pragma unroll
    for (int off = 16; off > 0; off >>= 1) {
        sum += __shfl_down_sync(0xffffffffu, sum, off);
        float ov = __shfl_down_sync(0xffffffffu, mval, off);
        int   oi = __shfl_down_sync(0xffffffffu, midx, off);
        if (ov > mval || (ov == mval && oi < midx)) { mval = ov; midx = oi; }
    }
    if (lane == 0) {
        g_sums[row] = sum;
        g_amax[row] = midx;
    }
}

// ---------------------------------------------------------------------------
// K2: one block per batch. PDL: prefetch weight slices into registers BEFORE
// the grid dependency sync (overlaps K1's drain), then SE + exact top-38,
// emitting packed task descriptors {row, aidx, lam}.
// ---------------------------------------------------------------------------
__global__ __launch_bounds__(256) void k2_se_topk(const float* __restrict__ w1,
                                                  const float* __restrict__ w2) {
    const int b = blockIdx.x;
    const int t = threadIdx.x;
    const int d    = t >> 4;
    const int part = t & 15;
    const int c0   = part * 16;

    // Prefetch weights (independent of K1) before the dependency sync.
    float w1v[16], w2v[16];
    #pragma unroll
    for (int k = 0; k < 16; k++) w1v[k] = __ldg(&w1[d * CC + c0 + k]);
    #pragma unroll
    for (int k = 0; k < 16; k++) w2v[k] = __ldg(&w2[t * 16 + k]);

    cudaGridDependencySynchronize();   // K1's g_sums/g_amax now visible

    __shared__ float s_pooled[CC];
    __shared__ float s_hidden[16];
    __shared__ float s_M[CC];

    s_pooled[t] = g_sums[b * CC + t] * (1.0f / (float)HW);
    __syncthreads();

    // fc1: 16-thread group per hidden unit, shfl-xor reduce within group
    {
        float acc = 0.0f;
        #pragma unroll
        for (int k = 0; k < 16; k++) acc += s_pooled[c0 + k] * w1v[k];
        #pragma unroll
        for (int off = 8; off > 0; off >>= 1)
            acc += __shfl_xor_sync(0xffffffffu, acc, off);
        if (part == 0) s_hidden[d] = fmaxf(acc, 0.0f);
    }
    __syncthreads();

    // fc2 + sigmoid
    {
        float acc = 0.0f;
        #pragma unroll
        for (int k = 0; k < 16; k++) acc += s_hidden[k] * w2v[k];
        s_M[t] = 1.0f / (1.0f + expf(-acc));
    }
    __syncthreads();

    const float m = s_M[t];
    int cnt = 0;
    for (int j = 0; j < CC; j++) {
        const float mj = s_M[j];
        cnt += (mj > m) || (mj == m && j < t);
    }
    if (cnt < TOPK) {
        const int row  = b * CC + t;
        const int aidx = g_amax[row];
        const int mh = aidx / WW;
        const int mw = aidx % WW;
        const int h1  = max(mh - 2, 0), h2  = min(mh + 2, HH - 1);
        const int w1b = max(mw - 2, 0), w2b = min(mw + 2, WW - 1);
        const int box = (h2 - h1 + 1) * (w2b - w1b + 1);
        const float lam = (float)HW / (float)(HW - box);
        g_task[b * TOPK + cnt] = make_int4(row, aidx, __float_as_int(lam), 0);
    }
}

// ---------------------------------------------------------------------------
// K3: 128-thread blocks, 4 warps/block, quarter-row per warp, all loads
// front-batched (MLP ~7). Single packed-task load (no dependent chain).
// ---------------------------------------------------------------------------
__global__ __launch_bounds__(128) void k3_apply(const float* __restrict__ x,
                                                float* __restrict__ out) {
    cudaGridDependencySynchronize();   // K2's g_task now visible

    const int warp = threadIdx.x >> 5;
    const int lane = threadIdx.x & 31;
    const int gw   = blockIdx.x * 4 + warp;
    const int sel  = gw >> 2;
    const int part = gw & 3;

    const int4 tk  = g_task[sel];
    const int row  = tk.x;
    const int aidx = tk.y;
    const float lam = __int_as_float(tk.z);
    const int mh = aidx / WW;
    const int mw = aidx % WW;
    const int h1  = max(mh - 2, 0), h2  = min(mh + 2, HH - 1);
    const int w1b = max(mw - 2, 0), w2b = min(mw + 2, WW - 1);

    const float4* __restrict__ xr  = (const float4*)(x   + (size_t)row * HW);
    float4*       __restrict__ orr = (float4*)      (out + (size_t)row * HW);
    const int q0 = part * QW;                 // [q0, q0+196)

    float4 v[6];
    #pragma unroll
    for (int k = 0; k < 6; k++) v[k] = __ldcs(&xr[q0 + k * 32 + lane]);
    float4 vt;
    const bool has_tail = (lane < 4);
    if (has_tail) vt = __ldcs(&xr[q0 + 192 + lane]);

    #pragma unroll
    for (int k = 0; k < 6; k++) {
        const int i0 = q0 + k * 32 + lane;
        const int p  = i0 << 2;
        const int r  = p / WW;
        const int c0 = p % WW;                // WW % 4 == 0: same image row
        const bool rin = (r >= h1) && (r <= h2);
        float4 o;
        o.x = (rin && c0     >= w1b && c0     <= w2b) ? 0.0f : v[k].x * lam;
        o.y = (rin && c0 + 1 >= w1b && c0 + 1 <= w2b) ? 0.0f : v[k].y * lam;
        o.z = (rin && c0 + 2 >= w1b && c0 + 2 <= w2b) ? 0.0f : v[k].z * lam;
        o.w = (rin && c0 + 3 >= w1b && c0 + 3 <= w2b) ? 0.0f : v[k].w * lam;
        __stcs(&orr[i0], o);
    }
    if (has_tail) {
        const int i0 = q0 + 192 + lane;
        const int p  = i0 << 2;
        const int r  = p / WW;
        const int c0 = p % WW;
        const bool rin = (r >= h1) && (r <= h2);
        float4 o;
        o.x = (rin && c0     >= w1b && c0     <= w2b) ? 0.0f : vt.x * lam;
        o.y = (rin && c0 + 1 >= w1b && c0 + 1 <= w2b) ? 0.0f : vt.y * lam;
        o.z = (rin && c0 + 2 >= w1b && c0 + 2 <= w2b) ? 0.0f : vt.z * lam;
        o.w = (rin && c0 + 3 >= w1b && c0 + 3 <= w2b) ? 0.0f : vt.w * lam;
        __stcs(&orr[i0], o);
    }
}

// ---------------------------------------------------------------------------
extern "C" void kernel_launch(void* const* d_in, const int* in_sizes, int n_in,
                              void* d_out, int out_size) {
    const float* x  = (const float*)d_in[0];
    const float* w1 = (const float*)d_in[1];
    const float* w2 = (const float*)d_in[2];
    float* out = (float*)d_out;

    k1_reduce_copy<<<NROWS / 8, 256>>>(x, out);   // 2048 blocks

    cudaLaunchAttribute attr[1];
    attr[0].id = cudaLaunchAttributeProgrammaticStreamSerialization;
    attr[0].val.programmaticStreamSerializationAllowed = 1;

    {   // K2 with PDL
        cudaLaunchConfig_t cfg = {};
        cfg.gridDim  = dim3(BB, 1, 1);
        cfg.blockDim = dim3(256, 1, 1);
        cfg.attrs    = attr;
        cfg.numAttrs = 1;
        cudaLaunchKernelEx(&cfg, k2_se_topk, w1, w2);
    }
    {   // K3 with PDL
        cudaLaunchConfig_t cfg = {};
        cfg.gridDim  = dim3(NSEL, 1, 1);          // 2432 blocks of 128
        cfg.blockDim = dim3(128, 1, 1);
        cfg.attrs    = attr;
        cfg.numAttrs = 1;
        cudaLaunchKernelEx(&cfg, k3_apply, x, out);
    }
}